// round 5
// baseline (speedup 1.0000x reference)
#include <cuda_runtime.h>

// VanillaRNN fused persistent kernel, v4.
// B=1024, T=512, I=64, H=128, O=10.
// Grid: 128 CTAs x 8 batch rows. Block: 512 threads (16 warps, 4/SMSP).
//
// Thread mapping: g = warp*2 + (lane&1) in [0,32): column group (4 cols
// {g, g+32, g+64, g+96}); seg = lane>>1 in [0,16): k-segment of 12 floats
// of the 192-wide concat(x_t, h_t).
//
// Same FFMA2 issue count per SMSP as v3 but 4 warps/SMSP -> latency hiding.
// Cross-segment reduction: 4-stage butterfly (xor 2,4,8,16); stages halve the
// live row set 8->4->2->1, final stage splits the 4 cols into 2. 30 shfl/thread.
// Lane finalizes 1 row x 2 cols.
//
// Physical smem layout per row: 16 segments of 12 floats padded to stride 14
// -> segment bases hit 16 distinct even banks; LDS.64 with 2-lane broadcast
// pairs = one conflict-free wavefront. Row stride 224 floats.
// Double-buffered state -> ONE __syncthreads per timestep.

#define ROWS 8
#define NTHREADS 512
#define HDIM 128
#define IDIM 64
#define TSTEPS 512
#define ODIM 10
#define SEGF 12
#define SEGP 14
#define RSTRIDE 224   // 16*14

__device__ __forceinline__ unsigned long long ffma2(unsigned long long a,
                                                    unsigned long long b,
                                                    unsigned long long c) {
    unsigned long long d;
    asm("fma.rn.f32x2 %0, %1, %2, %3;" : "=l"(d) : "l"(a), "l"(b), "l"(c));
    return d;
}

__device__ __forceinline__ unsigned long long packf2(float lo, float hi) {
    return ((unsigned long long)__float_as_uint(hi) << 32) |
           (unsigned long long)__float_as_uint(lo);
}

__device__ __forceinline__ float sum2(unsigned long long a) {
    return __uint_as_float((unsigned)a) + __uint_as_float((unsigned)(a >> 32));
}

__device__ __forceinline__ float fast_tanh(float z) {
    float e = __expf(2.0f * z);
    return 1.0f - __fdividef(2.0f, e + 1.0f);
}

__device__ __forceinline__ int physk(int k) { return k + 2 * (k / SEGF); }

__device__ __forceinline__ float wpick(const float* __restrict__ W_hx,
                                       const float* __restrict__ W_hh,
                                       int o, int k) {
    return (k < IDIM) ? W_hx[o * IDIM + k] : W_hh[o * HDIM + (k - IDIM)];
}

__global__ void __launch_bounds__(NTHREADS, 1)
rnn_fused_kernel(const float* __restrict__ x,
                 const float* __restrict__ W_hx,
                 const float* __restrict__ W_hh,
                 const float* __restrict__ b_hh,
                 const float* __restrict__ W_ph,
                 const float* __restrict__ b_ph,
                 float* __restrict__ out) {
    __shared__ __align__(16) float buf[2][ROWS][RSTRIDE];

    const int tid  = threadIdx.x;
    const int lane = tid & 31;
    const int warp = tid >> 5;
    const int g    = warp * 2 + (lane & 1);   // col group 0..31
    const int seg  = lane >> 1;               // k-segment 0..15
    const int kb   = seg * SEGF;
    const int b0r  = blockIdx.x * ROWS;

    // ---- weights: 4 cols x 6 packed f32x2 (12 logical k per col)
    unsigned long long w[4][6];
#pragma unroll
    for (int c = 0; c < 4; c++) {
        const int o = g + 32 * c;
#pragma unroll
        for (int j = 0; j < 6; j++) {
            const int k0 = kb + 2 * j;
            w[c][j] = packf2(wpick(W_hx, W_hh, o, k0),
                             wpick(W_hx, W_hh, o, k0 + 1));
        }
    }

    // Final ownership after the 4-stage tree:
    // seg bits b0,b1,b2 -> row = 4*b0+2*b1+b2 ; bit b3 -> col pair {2*b3, 2*b3+1}
    const int sb0 = seg & 1, sb1 = (seg >> 1) & 1, sb2 = (seg >> 2) & 1,
              sb3 = (seg >> 3) & 1;
    const int mstar = 4 * sb0 + 2 * sb1 + sb2;
    const int cf0 = 2 * sb3;            // first of the two final cols
    const int of0 = g + 32 * cf0;
    const int of1 = of0 + 32;
    const float bb0 = b_hh[of0];
    const float bb1 = b_hh[of1];
    const int ph0 = physk(IDIM + of0);
    const int ph1 = physk(IDIM + of1);

    // ---- zero both buffers (h0 = 0)
    for (int i = tid; i < 2 * ROWS * RSTRIDE; i += NTHREADS)
        ((float*)buf)[i] = 0.0f;

    // ---- x loader: tids [0,256): row xr, float2 chunk c2 (never straddles seg)
    const int xr  = tid >> 5;            // valid for tid<256: 0..7
    const int c2  = (tid & 31) * 2;      // 0..62
    const int pc2 = c2 + 2 * (c2 / SEGF);
    const float* xrow = x + (size_t)(b0r + (xr & 7)) * TSTEPS * IDIM;
    const bool loader = (tid < 256);

    if (loader)
        *(float2*)&buf[0][xr][pc2] = *(const float2*)(xrow + c2);
    __syncthreads();

    int p = 0;
    for (int t = 0; t < TSTEPS; t++) {
        float2 xn;
        if (loader) {
            const int tn = (t + 1 < TSTEPS) ? t + 1 : TSTEPS - 1;
            xn = *(const float2*)(xrow + (size_t)tn * IDIM + c2);
        }

        // ---- accumulate: 8 rows x 4 cols over this thread's 12 k's
        float s[ROWS][4];
#pragma unroll
        for (int m = 0; m < ROWS; m++) {
            const unsigned long long* pp =
                (const unsigned long long*)&buf[p][m][seg * SEGP];
            unsigned long long v0 = pp[0], v1 = pp[1], v2 = pp[2];
            unsigned long long v3 = pp[3], v4 = pp[4], v5 = pp[5];
            unsigned long long a0, a1, a2, a3;
            a0 = ffma2(v0, w[0][0], 0ull);
            a1 = ffma2(v0, w[1][0], 0ull);
            a2 = ffma2(v0, w[2][0], 0ull);
            a3 = ffma2(v0, w[3][0], 0ull);
            a0 = ffma2(v1, w[0][1], a0);
            a1 = ffma2(v1, w[1][1], a1);
            a2 = ffma2(v1, w[2][1], a2);
            a3 = ffma2(v1, w[3][1], a3);
            a0 = ffma2(v2, w[0][2], a0);
            a1 = ffma2(v2, w[1][2], a1);
            a2 = ffma2(v2, w[2][2], a2);
            a3 = ffma2(v2, w[3][2], a3);
            a0 = ffma2(v3, w[0][3], a0);
            a1 = ffma2(v3, w[1][3], a1);
            a2 = ffma2(v3, w[2][3], a2);
            a3 = ffma2(v3, w[3][3], a3);
            a0 = ffma2(v4, w[0][4], a0);
            a1 = ffma2(v4, w[1][4], a1);
            a2 = ffma2(v4, w[2][4], a2);
            a3 = ffma2(v4, w[3][4], a3);
            a0 = ffma2(v5, w[0][5], a0);
            a1 = ffma2(v5, w[1][5], a1);
            a2 = ffma2(v5, w[2][5], a2);
            a3 = ffma2(v5, w[3][5], a3);
            s[m][0] = sum2(a0); s[m][1] = sum2(a1);
            s[m][2] = sum2(a2); s[m][3] = sum2(a3);
        }

        // ---- 4-stage butterfly tree over 16 segments (seg bits = lane bits 1..4)
        // stage 0: xor 2, rows 8 -> 4
        float r1[4][4];
        {
            const bool low = (sb0 == 0);
#pragma unroll
            for (int r = 0; r < 4; r++)
#pragma unroll
                for (int c = 0; c < 4; c++) {
                    float send = low ? s[r + 4][c] : s[r][c];
                    float recv = __shfl_xor_sync(0xffffffffu, send, 2);
                    float keep = low ? s[r][c] : s[r + 4][c];
                    r1[r][c] = keep + recv;
                }
        }
        // stage 1: xor 4, rows 4 -> 2
        float r2[2][4];
        {
            const bool low = (sb1 == 0);
#pragma unroll
            for (int r = 0; r < 2; r++)
#pragma unroll
                for (int c = 0; c < 4; c++) {
                    float send = low ? r1[r + 2][c] : r1[r][c];
                    float recv = __shfl_xor_sync(0xffffffffu, send, 4);
                    float keep = low ? r1[r][c] : r1[r + 2][c];
                    r2[r][c] = keep + recv;
                }
        }
        // stage 2: xor 8, rows 2 -> 1
        float r3[4];
        {
            const bool low = (sb2 == 0);
#pragma unroll
            for (int c = 0; c < 4; c++) {
                float send = low ? r2[1][c] : r2[0][c];
                float recv = __shfl_xor_sync(0xffffffffu, send, 8);
                float keep = low ? r2[0][c] : r2[1][c];
                r3[c] = keep + recv;
            }
        }
        // stage 3: xor 16, cols 4 -> 2
        float f0, f1;
        {
            const bool low = (sb3 == 0);
            float send0 = low ? r3[2] : r3[0];
            float send1 = low ? r3[3] : r3[1];
            float recv0 = __shfl_xor_sync(0xffffffffu, send0, 16);
            float recv1 = __shfl_xor_sync(0xffffffffu, send1, 16);
            f0 = (low ? r3[0] : r3[2]) + recv0;
            f1 = (low ? r3[1] : r3[3]) + recv1;
        }

        // ---- finalize: row mstar, cols of0, of1
        const int q = p ^ 1;
        buf[q][mstar][ph0] = fast_tanh(f0 + bb0);
        buf[q][mstar][ph1] = fast_tanh(f1 + bb1);

        if (loader) *(float2*)&buf[q][xr][pc2] = xn;

        __syncthreads();
        p = q;
    }

    // ---- final projection
    if (tid < ROWS * ODIM) {
        const int m = tid / ODIM;
        const int j = tid % ODIM;
        float s = b_ph[j];
#pragma unroll 4
        for (int k = 0; k < HDIM; k++)
            s += buf[p][m][physk(IDIM + k)] * W_ph[j * HDIM + k];
        out[(size_t)(b0r + m) * ODIM + j] = s;
    }
}

extern "C" void kernel_launch(void* const* d_in, const int* in_sizes, int n_in,
                              void* d_out, int out_size) {
    const float* x    = (const float*)d_in[0];
    const float* W_hx = (const float*)d_in[1];
    const float* W_hh = (const float*)d_in[2];
    const float* b_hh = (const float*)d_in[3];
    const float* W_ph = (const float*)d_in[4];
    const float* b_ph = (const float*)d_in[5];
    float* out = (float*)d_out;

    rnn_fused_kernel<<<1024 / ROWS, NTHREADS>>>(x, W_hx, W_hh, b_hh, W_ph, b_ph, out);
}

// round 6
// speedup vs baseline: 1.1576x; 1.1576x over previous
#include <cuda_runtime.h>

// VanillaRNN fused persistent kernel, v5.
// B=1024, T=512, I=64, H=128, O=10.
// Grid: 256 CTAs x 4 batch rows. Block: 256 threads, TWO CTAs per SM
// (__launch_bounds__(256,2), <=128 regs). The second resident CTA is an
// INDEPENDENT recurrence chain that fills this CTA's barrier/shuffle/LDS
// latency holes -- the per-SMSP FFMA2 floor (2 CTAs x 2 warps x 384 = 1536
// cyc/step) is unchanged, the exposed latency (~1450 cyc/step in v3) overlaps.
//
// Thread mapping (v3 style): g = warp*4 + (lane&3) in [0,32): column group,
// owns cols {g, g+32, g+64, g+96}; seg = lane>>2 in [0,8): 24-wide k-segment
// of the 192-wide concat(x_t, h_t).
// Rows processed in two pairs {0,2} then {1,3} with the stage-0 butterfly
// folded in between -> peak accumulator liveness 8 floats (register relief).
// Tree: xor4 (pair), xor8 (rows->1), xor16 (cols 4->2): 14 shfl/thread.
// Lane finalizes row 2*sb0+sb1, cols {g+64*sb2, g+32+64*sb2}.

#define ROWS 4
#define NTHREADS 256
#define HDIM 128
#define IDIM 64
#define TSTEPS 512
#define ODIM 10
#define SEGF 24
#define SEGP 28
#define RSTRIDE 228

__device__ __forceinline__ unsigned long long ffma2(unsigned long long a,
                                                    unsigned long long b,
                                                    unsigned long long c) {
    unsigned long long d;
    asm("fma.rn.f32x2 %0, %1, %2, %3;" : "=l"(d) : "l"(a), "l"(b), "l"(c));
    return d;
}

__device__ __forceinline__ unsigned long long packf2(float lo, float hi) {
    return ((unsigned long long)__float_as_uint(hi) << 32) |
           (unsigned long long)__float_as_uint(lo);
}

__device__ __forceinline__ float sum2(unsigned long long a) {
    return __uint_as_float((unsigned)a) + __uint_as_float((unsigned)(a >> 32));
}

__device__ __forceinline__ float fast_tanh(float z) {
    float e = __expf(2.0f * z);
    return 1.0f - __fdividef(2.0f, e + 1.0f);
}

__device__ __forceinline__ int physk(int k) { return k + 4 * (k / SEGF); }

__device__ __forceinline__ float wpick(const float* __restrict__ W_hx,
                                       const float* __restrict__ W_hh,
                                       int o, int k) {
    return (k < IDIM) ? W_hx[o * IDIM + k] : W_hh[o * HDIM + (k - IDIM)];
}

// accumulate one row's 24-k segment for 4 cols
__device__ __forceinline__ void row_acc(const float* __restrict__ rowbase,
                                        int segoff,
                                        const unsigned long long w[4][12],
                                        float sv[4]) {
    const ulonglong2* pp = (const ulonglong2*)(rowbase + segoff);
    unsigned long long a0 = 0ull, a1 = 0ull, a2 = 0ull, a3 = 0ull;
#pragma unroll
    for (int i = 0; i < 6; i++) {
        ulonglong2 v = pp[i];
        a0 = ffma2(v.x, w[0][2 * i], a0);
        a1 = ffma2(v.x, w[1][2 * i], a1);
        a2 = ffma2(v.x, w[2][2 * i], a2);
        a3 = ffma2(v.x, w[3][2 * i], a3);
        a0 = ffma2(v.y, w[0][2 * i + 1], a0);
        a1 = ffma2(v.y, w[1][2 * i + 1], a1);
        a2 = ffma2(v.y, w[2][2 * i + 1], a2);
        a3 = ffma2(v.y, w[3][2 * i + 1], a3);
    }
    sv[0] = sum2(a0); sv[1] = sum2(a1); sv[2] = sum2(a2); sv[3] = sum2(a3);
}

__global__ void __launch_bounds__(NTHREADS, 2)
rnn_fused_kernel(const float* __restrict__ x,
                 const float* __restrict__ W_hx,
                 const float* __restrict__ W_hh,
                 const float* __restrict__ b_hh,
                 const float* __restrict__ W_ph,
                 const float* __restrict__ b_ph,
                 float* __restrict__ out) {
    __shared__ __align__(16) float buf[2][ROWS][RSTRIDE];

    const int tid  = threadIdx.x;
    const int lane = tid & 31;
    const int warp = tid >> 5;
    const int g    = warp * 4 + (lane & 3);   // col group 0..31
    const int seg  = lane >> 2;               // k-segment 0..7
    const int kb   = seg * SEGF;
    const int b0r  = blockIdx.x * ROWS;

    // ---- weights: 4 cols x 12 packed f32x2 (24 logical k per col) = 96 regs
    unsigned long long w[4][12];
#pragma unroll
    for (int c = 0; c < 4; c++) {
        const int o = g + 32 * c;
#pragma unroll
        for (int j = 0; j < 12; j++) {
            const int k0 = kb + 2 * j;
            w[c][j] = packf2(wpick(W_hx, W_hh, o, k0),
                             wpick(W_hx, W_hh, o, k0 + 1));
        }
    }

    const int sb0 = seg & 1, sb1 = (seg >> 1) & 1, sb2 = (seg >> 2) & 1;
    const int mstar = 2 * sb0 + sb1;          // row this lane finalizes
    const int of0 = g + 64 * sb2;             // its two output columns
    const int of1 = of0 + 32;
    const float bb0 = b_hh[of0];
    const float bb1 = b_hh[of1];
    const int ph0 = physk(IDIM + of0);
    const int ph1 = physk(IDIM + of1);
    const int segoff = seg * SEGP;

    // ---- zero both buffers (h0 = 0)
    for (int i = tid; i < 2 * ROWS * RSTRIDE; i += NTHREADS)
        ((float*)buf)[i] = 0.0f;

    // ---- x loader: tid<64, row xr, float4 chunk c4 (24%4==0 -> no straddle)
    const int xr  = (tid >> 4) & 3;
    const int c4  = (tid & 15) * 4;
    const int pc4 = c4 + 4 * (c4 / SEGF);
    const bool loader = (tid < 64);
    const float* xrow = x + (size_t)(b0r + xr) * TSTEPS * IDIM;

    if (loader)
        *(float4*)&buf[0][xr][pc4] = *(const float4*)(xrow + c4);
    __syncthreads();

    int p = 0;
    for (int t = 0; t < TSTEPS; t++) {
        float4 xn;
        if (loader) {
            const int tn = (t + 1 < TSTEPS) ? t + 1 : TSTEPS - 1;
            xn = *(const float4*)(xrow + (size_t)tn * IDIM + c4);
        }

        const float* base0 = &buf[p][0][0];
        const bool low0 = (sb0 == 0);

        // ---- pair A: rows {0, 2}; stage-0 butterfly folded in (xor 4)
        float ra[4];
        {
            float sA[4], sB[4];
            row_acc(base0 + 0 * RSTRIDE, segoff, w, sA);
            row_acc(base0 + 2 * RSTRIDE, segoff, w, sB);
#pragma unroll
            for (int c = 0; c < 4; c++) {
                float send = low0 ? sB[c] : sA[c];
                float recv = __shfl_xor_sync(0xffffffffu, send, 4);
                ra[c] = (low0 ? sA[c] : sB[c]) + recv;
            }
        }
        // ---- pair B: rows {1, 3}
        float rb[4];
        {
            float sA[4], sB[4];
            row_acc(base0 + 1 * RSTRIDE, segoff, w, sA);
            row_acc(base0 + 3 * RSTRIDE, segoff, w, sB);
#pragma unroll
            for (int c = 0; c < 4; c++) {
                float send = low0 ? sB[c] : sA[c];
                float recv = __shfl_xor_sync(0xffffffffu, send, 4);
                rb[c] = (low0 ? sA[c] : sB[c]) + recv;
            }
        }

        // ---- stage 1 (xor 8): rows 2 -> 1
        float rc[4];
        {
            const bool low = (sb1 == 0);
#pragma unroll
            for (int c = 0; c < 4; c++) {
                float send = low ? rb[c] : ra[c];
                float recv = __shfl_xor_sync(0xffffffffu, send, 8);
                rc[c] = (low ? ra[c] : rb[c]) + recv;
            }
        }
        // ---- stage 2 (xor 16): cols 4 -> 2
        float f0, f1;
        {
            const bool low = (sb2 == 0);
            float send0 = low ? rc[2] : rc[0];
            float send1 = low ? rc[3] : rc[1];
            float recv0 = __shfl_xor_sync(0xffffffffu, send0, 16);
            float recv1 = __shfl_xor_sync(0xffffffffu, send1, 16);
            f0 = (low ? rc[0] : rc[2]) + recv0;
            f1 = (low ? rc[1] : rc[3]) + recv1;
        }

        // ---- finalize: row mstar, cols of0, of1
        const int q = p ^ 1;
        buf[q][mstar][ph0] = fast_tanh(f0 + bb0);
        buf[q][mstar][ph1] = fast_tanh(f1 + bb1);

        if (loader) *(float4*)&buf[q][xr][pc4] = xn;

        __syncthreads();
        p = q;
    }

    // ---- final projection: out[b0r+m][j] = b_ph[j] + sum_k h[m][k]*W_ph[j][k]
    if (tid < ROWS * ODIM) {
        const int m = tid / ODIM;
        const int j = tid % ODIM;
        float s = b_ph[j];
#pragma unroll 4
        for (int k = 0; k < HDIM; k++)
            s += buf[p][m][physk(IDIM + k)] * W_ph[j * HDIM + k];
        out[(size_t)(b0r + m) * ODIM + j] = s;
    }
}

extern "C" void kernel_launch(void* const* d_in, const int* in_sizes, int n_in,
                              void* d_out, int out_size) {
    const float* x    = (const float*)d_in[0];
    const float* W_hx = (const float*)d_in[1];
    const float* W_hh = (const float*)d_in[2];
    const float* b_hh = (const float*)d_in[3];
    const float* W_ph = (const float*)d_in[4];
    const float* b_ph = (const float*)d_in[5];
    float* out = (float*)d_out;

    rnn_fused_kernel<<<1024 / ROWS, NTHREADS>>>(x, W_hx, W_hh, b_hh, W_ph, b_ph, out);
}